// round 8
// baseline (speedup 1.0000x reference)
#include <cuda_runtime.h>
#include <cuda_fp16.h>
#include <stdint.h>
#include <math.h>

#define IMG   320
#define NPIX  1024
#define YROWB 144           // 72 halfs; stride%128=16 -> conflict-free ldmatrix

// shared layout (bytes): red overlays timg (timg dead after build)
#define SM_TIMG 0           // 12288 B (red: float4[512]=8KB after sync)
#define SM_AUX2 12288       // u32[4096]: per col-pair {I0e,I0o,I1e,I1o,I2e,I2o,sqe,sqo}
#define SM_Y    28672       // half[1024][72]  (147456 B)
#define SM_LUT  (28672 + NPIX * YROWB)          // float2[288] = 2304 B
#define SMEM_TOTAL (SM_LUT + 288 * 8)           // 178432

#define LUT_N    288
#define LUT_BIAS 1872       // (117 << 4): first bin at dd = 2^-10

typedef unsigned long long ull;

__device__ __forceinline__ uint32_t smem_u32(const void* p) {
    uint32_t a;
    asm("{ .reg .u64 t; cvta.to.shared.u64 t, %1; cvt.u32.u64 %0, t; }" : "=r"(a) : "l"(p));
    return a;
}
__device__ __forceinline__ ull fma2(ull a, ull b, ull c) {
    ull d; asm("fma.rn.f32x2 %0, %1, %2, %3;" : "=l"(d) : "l"(a), "l"(b), "l"(c));
    return d;
}
__device__ __forceinline__ ull add2(ull a, ull b) {
    ull d; asm("add.rn.f32x2 %0, %1, %2;" : "=l"(d) : "l"(a), "l"(b));
    return d;
}
__device__ __forceinline__ ull pack2(float lo, float hi) {
    ull d; asm("mov.b64 %0, {%1, %2};" : "=l"(d) : "f"(lo), "f"(hi));
    return d;
}
__device__ __forceinline__ float2 unpack2(ull v) {
    float lo, hi; asm("mov.b64 {%0, %1}, %2;" : "=f"(lo), "=f"(hi) : "l"(v));
    return make_float2(lo, hi);
}

#define LDSM4(r, addr) \
    asm volatile("ldmatrix.sync.aligned.m8n8.x4.shared.b16 {%0,%1,%2,%3}, [%4];" \
        : "=r"((r)[0]), "=r"((r)[1]), "=r"((r)[2]), "=r"((r)[3]) : "r"(addr))
#define LDSM2(r, addr) \
    asm volatile("ldmatrix.sync.aligned.m8n8.x2.shared.b16 {%0,%1}, [%2];" \
        : "=r"((r)[0]), "=r"((r)[1]) : "r"(addr))
#define MMA16816(c, a, b0, b1) \
    asm volatile("mma.sync.aligned.m16n8k16.row.col.f32.f16.f16.f32 " \
        "{%0,%1,%2,%3}, {%4,%5,%6,%7}, {%8,%9}, {%0,%1,%2,%3};" \
        : "+f"((c)[0]), "+f"((c)[1]), "+f"((c)[2]), "+f"((c)[3]) \
        : "r"((a)[0]), "r"((a)[1]), "r"((a)[2]), "r"((a)[3]), "r"(b0), "r"(b1))
#define MMA16808(c, a, b0) \
    asm volatile("mma.sync.aligned.m16n8k8.row.col.f32.f16.f16.f32 " \
        "{%0,%1,%2,%3}, {%4,%5}, {%6}, {%0,%1,%2,%3};" \
        : "+f"((c)[0]), "+f"((c)[1]), "+f"((c)[2]), "+f"((c)[3]) \
        : "r"((a)[0]), "r"((a)[1]), "r"(b0))

__global__ __launch_bounds__(512, 1)
void nlm_hmma_kernel(const float* __restrict__ img, float* __restrict__ out)
{
    extern __shared__ char sm[];
    float*    timg  = (float*)(sm + SM_TIMG);
    float4*   red   = (float4*)(sm + SM_TIMG);     // overlays timg after build
    uint32_t* aux2u = (uint32_t*)(sm + SM_AUX2);
    char*     Yb    = sm + SM_Y;
    float2*   lut   = (float2*)(sm + SM_LUT);

    const int bid  = blockIdx.x;
    const int tile = bid >> 2, nb = bid & 3;       // 256 rows per CTA
    const int ti = tile / 10, tj = tile % 10;
    const int tid = threadIdx.x;
    const int gb = ti * 32 * IMG + tj * 32;

    // ---- build w(dd) = exp(-sqrt(dd)) LUT: 18 octaves x 16 sub-bins, linear ----
    if (tid < LUT_N) {
        int o = tid >> 4, sub = tid & 15;
        double t0 = exp2((double)(o - 10)) * (1.0 + sub / 16.0);
        double h  = exp2((double)(o - 10)) / 16.0;
        double f0 = exp(-sqrt(t0));
        double f1 = exp(-sqrt(t0 + h));
        double fm = exp(-sqrt(t0 + 0.5 * h));
        double b  = (f1 - f0) / h;
        double a  = f0 - b * t0;
        a += 0.5 * (fm - (a + b * (t0 + 0.5 * h)));   // midpoint centering
        lut[tid] = make_float2((float)a, (float)b);
    }

    // ---- tile image -> smem ----
    for (int i = tid; i < 3 * NPIX; i += 512) {
        int ch = i >> 10, pix = i & 1023;
        timg[i] = img[ch * (IMG * IMG) + gb + (pix >> 5) * IMG + (pix & 31)];
    }
    __syncthreads();

    // ---- build fp16 features Y[1024][72] + pair-interleaved aux ----
    for (int p = tid; p < NPIX; p += 512) {
        int r = p >> 5, c = p & 31;
        __half hl[72];
        float sq = 0.f;
        #pragma unroll
        for (int k = 0; k < 25; k++) {
            if (k == 12) continue;
            int kk = (k < 12) ? k : k - 1;
            int rr = min(max(r + k / 5 - 2, 0), 31);
            int cc = min(max(c + k % 5 - 2, 0), 31);
            int off = rr * 32 + cc;
            #pragma unroll
            for (int ch = 0; ch < 3; ch++) {
                float x = timg[ch * NPIX + off];
                __half h = __float2half_rn(x);
                float xr = __half2float(h);
                sq = fmaf(xr, xr, sq);
                hl[ch * 24 + kk] = h;
            }
        }
        __half2* yrow = (__half2*)(Yb + p * YROWB);
        #pragma unroll
        for (int i = 0; i < 36; i++)
            yrow[i] = __halves2half2(hl[2 * i], hl[2 * i + 1]);
        int ab = (p >> 1) * 8 + (p & 1);
        aux2u[ab + 0] = __float_as_uint(timg[p]);
        aux2u[ab + 2] = __float_as_uint(timg[NPIX + p]);
        aux2u[ab + 4] = __float_as_uint(timg[2 * NPIX + p]);
        aux2u[ab + 6] = __float_as_uint(sq);
    }
    __syncthreads();

    // ---- warp geometry: 16 warps = 8 n-subblocks x 2 m-halves ----
    const int wid = tid >> 5, lane = tid & 31;
    const int wn = wid >> 1;
    const int wm2 = wid & 1;
    const int grb = nb * 256 + wn * 32;
    const uint32_t ybase = smem_u32(Yb);

    // ---- A fragments hoisted ----
    uint32_t a[2][4][4], a8[2][2];
    {
        int row = lane & 15;
        int cb  = (lane >> 4) << 4;
        #pragma unroll
        for (int nt = 0; nt < 2; nt++) {
            #pragma unroll
            for (int ks = 0; ks < 4; ks++)
                LDSM4(a[nt][ks], ybase + (uint32_t)(grb + nt * 16 + row) * YROWB + ks * 32 + cb);
            LDSM2(a8[nt], ybase + (uint32_t)(grb + nt * 16 + row) * YROWB + 128);
        }
    }

    // row norms + diag row ids, hoisted
    float sN[2][2];
    int   gR[2][2];
    #pragma unroll
    for (int nt = 0; nt < 2; nt++)
        #pragma unroll
        for (int h = 0; h < 2; h++) {
            int gr = grb + nt * 16 + h * 8 + (lane >> 2);
            gR[nt][h] = gr;
            sN[nt][h] = __uint_as_float(aux2u[(gr >> 1) * 8 + 6 + (gr & 1)]);
        }

    ull den2[2][2] = {{0ull,0ull},{0ull,0ull}};
    ull rr0[2][2]  = {{0ull,0ull},{0ull,0ull}};
    ull rr1[2][2]  = {{0ull,0ull},{0ull,0ull}};
    ull rr2[2][2]  = {{0ull,0ull},{0ull,0ull}};

    // ---- stream m: 8 blocks of 128; warp's 64-col half in 2 groups of 32 ----
    for (int mb = 0; mb < 8; mb++) {
        #pragma unroll
        for (int g = 0; g < 2; g++) {
            const int mgb = mb * 128 + wm2 * 64 + g * 32;
            float c[2][4][4];
            #pragma unroll
            for (int nt = 0; nt < 2; nt++)
                #pragma unroll
                for (int mt = 0; mt < 4; mt++)
                    c[nt][mt][0] = c[nt][mt][1] = c[nt][mt][2] = c[nt][mt][3] = 0.f;

            #pragma unroll
            for (int ks = 0; ks < 4; ks++) {
                uint32_t b[8];
                #pragma unroll
                for (int bt = 0; bt < 2; bt++) {
                    int row = mgb + bt * 16 + (lane & 7) + ((lane >> 4) << 3);
                    int cb  = ks * 32 + (((lane >> 3) & 1) << 4);
                    LDSM4(&b[bt * 4], ybase + (uint32_t)row * YROWB + cb);
                }
                #pragma unroll
                for (int nt = 0; nt < 2; nt++)
                    #pragma unroll
                    for (int mt = 0; mt < 4; mt++) {
                        int bi = (mt >> 1) * 4 + (mt & 1) * 2;
                        MMA16816(c[nt][mt], a[nt][ks], b[bi], b[bi + 1]);
                    }
            }
            {   // k8 tail (cols 64..71)
                uint32_t b8[4];
                int row = mgb + (lane >> 3) * 8 + (lane & 7);
                LDSM4(b8, ybase + (uint32_t)row * YROWB + 128);
                #pragma unroll
                for (int nt = 0; nt < 2; nt++)
                    #pragma unroll
                    for (int mt = 0; mt < 4; mt++)
                        MMA16808(c[nt][mt], a8[nt], b8[mt]);
            }

            // ---- epilogue: LUT weights (no MUFU), packed accumulation ----
            const bool dg = (mgb == grb);           // warp-uniform diag block
            #pragma unroll
            for (int mt = 0; mt < 4; mt++) {
                const int c0 = mgb + mt * 8 + ((lane & 3) << 1);
                const ulonglong2* ap = (const ulonglong2*)(aux2u + (c0 >> 1) * 8);
                ulonglong2 v01 = ap[0];             // (I0 pair, I1 pair)
                ulonglong2 v23 = ap[1];             // (I2 pair, sq pair)
                float2 qm = unpack2(v23.y);
                #pragma unroll
                for (int nt = 0; nt < 2; nt++)
                    #pragma unroll
                    for (int h = 0; h < 2; h++) {
                        float s  = sN[nt][h];
                        float d0 = fmaf(c[nt][mt][h * 2 + 0], -2.f, s + qm.x);
                        float d1 = fmaf(c[nt][mt][h * 2 + 1], -2.f, s + qm.y);
                        int i0 = min(max((int)(__float_as_uint(d0) >> 19) - LUT_BIAS, 0), LUT_N - 1);
                        int i1 = min(max((int)(__float_as_uint(d1) >> 19) - LUT_BIAS, 0), LUT_N - 1);
                        float2 e0 = lut[i0];
                        float2 e1 = lut[i1];
                        float w0 = fmaf(d0, e0.y, e0.x);
                        float w1 = fmaf(d1, e1.y, e1.x);
                        if (dg) {                   // kills diag
                            if (gR[nt][h] == c0)     w0 = 0.f;
                            if (gR[nt][h] == c0 + 1) w1 = 0.f;
                        }
                        ull w2 = pack2(w0, w1);
                        den2[nt][h] = add2(den2[nt][h], w2);
                        rr0[nt][h] = fma2(w2, v01.x, rr0[nt][h]);
                        rr1[nt][h] = fma2(w2, v01.y, rr1[nt][h]);
                        rr2[nt][h] = fma2(w2, v23.x, rr2[nt][h]);
                    }
            }
        }
    }

    __syncthreads();   // timg dead before red overlay

    // ---- horizontal combine + quad reduce + cross-half via smem ----
    #pragma unroll
    for (int nt = 0; nt < 2; nt++)
        #pragma unroll
        for (int h = 0; h < 2; h++) {
            float2 fd = unpack2(den2[nt][h]);
            float2 f0 = unpack2(rr0[nt][h]);
            float2 f1 = unpack2(rr1[nt][h]);
            float2 f2 = unpack2(rr2[nt][h]);
            float d = fd.x + fd.y, x = f0.x + f0.y, y = f1.x + f1.y, z = f2.x + f2.y;
            #pragma unroll
            for (int off = 1; off <= 2; off <<= 1) {
                d += __shfl_xor_sync(0xFFFFFFFFu, d, off);
                x += __shfl_xor_sync(0xFFFFFFFFu, x, off);
                y += __shfl_xor_sync(0xFFFFFFFFu, y, off);
                z += __shfl_xor_sync(0xFFFFFFFFu, z, off);
            }
            if ((lane & 3) == 0) {
                int rl = wn * 32 + nt * 16 + h * 8 + (lane >> 2);
                red[wm2 * 256 + rl] = make_float4(x, y, z, d);
            }
        }
    __syncthreads();

    if (tid < 256) {
        float4 p0 = red[tid], p1 = red[256 + tid];
        float inv = 1.f / (p0.w + p1.w);
        int n = nb * 256 + tid;
        int gp = gb + (n >> 5) * IMG + (n & 31);
        out[gp]                 = (p0.x + p1.x) * inv;
        out[IMG * IMG + gp]     = (p0.y + p1.y) * inv;
        out[2 * IMG * IMG + gp] = (p0.z + p1.z) * inv;
    }
}

extern "C" void kernel_launch(void* const* d_in, const int* in_sizes, int n_in,
                              void* d_out, int out_size)
{
    (void)in_sizes; (void)n_in; (void)out_size;
    const float* img = (const float*)d_in[0];
    float* out = (float*)d_out;
    cudaFuncSetAttribute(nlm_hmma_kernel, cudaFuncAttributeMaxDynamicSharedMemorySize, SMEM_TOTAL);
    nlm_hmma_kernel<<<400, 512, SMEM_TOTAL>>>(img, out);
}

// round 9
// speedup vs baseline: 1.3095x; 1.3095x over previous
#include <cuda_runtime.h>
#include <cuda_fp16.h>
#include <stdint.h>
#include <math.h>

#define IMG   320
#define NPIX  1024
#define YROWB 144           // 72 halfs; stride%128=16 -> conflict-free ldmatrix

// shared layout (bytes): red overlays timg (timg dead after build)
#define SM_TIMG 0           // 12288 B (red: float4[512]=8KB after sync)
#define SM_AUX2 12288       // u32[4096]: per col-pair {I0e,I0o,I1e,I1o,I2e,I2o,sq'e,sq'o}
#define SM_Y    28672       // half[1024][72]
#define SMEM_TOTAL (28672 + NPIX * YROWB)   // 176128

#define LOG2E2  2.0813689810056077f     // (log2 e)^2
#define NEG2L2 (-4.1627379620112153f)   // -2*(log2 e)^2

typedef unsigned long long ull;

__device__ __forceinline__ uint32_t smem_u32(const void* p) {
    uint32_t a;
    asm("{ .reg .u64 t; cvta.to.shared.u64 t, %1; cvt.u32.u64 %0, t; }" : "=r"(a) : "l"(p));
    return a;
}
__device__ __forceinline__ ull fma2(ull a, ull b, ull c) {
    ull d; asm("fma.rn.f32x2 %0, %1, %2, %3;" : "=l"(d) : "l"(a), "l"(b), "l"(c));
    return d;
}
__device__ __forceinline__ ull add2(ull a, ull b) {
    ull d; asm("add.rn.f32x2 %0, %1, %2;" : "=l"(d) : "l"(a), "l"(b));
    return d;
}
__device__ __forceinline__ ull pack2(float lo, float hi) {
    ull d; asm("mov.b64 %0, {%1, %2};" : "=l"(d) : "f"(lo), "f"(hi));
    return d;
}
__device__ __forceinline__ float2 unpack2(ull v) {
    float lo, hi; asm("mov.b64 {%0, %1}, %2;" : "=f"(lo), "=f"(hi) : "l"(v));
    return make_float2(lo, hi);
}
__device__ __forceinline__ float sqrta(float x) {
    float y; asm("sqrt.approx.f32 %0, %1;" : "=f"(y) : "f"(x)); return y;
}
__device__ __forceinline__ uint32_t cvt_h2(float hi, float lo) {   // h1=hi, h0=lo
    uint32_t r; asm("cvt.rn.f16x2.f32 %0, %1, %2;" : "=r"(r) : "f"(hi), "f"(lo));
    return r;
}
__device__ __forceinline__ uint32_t ex2h2(uint32_t a) {            // MUFU, 2 results
    uint32_t r; asm("ex2.approx.f16x2 %0, %1;" : "=r"(r) : "r"(a));
    return r;
}
__device__ __forceinline__ float2 h2f2(uint32_t h2) {
    __half2 hh = *reinterpret_cast<__half2*>(&h2);
    return make_float2(__low2float(hh), __high2float(hh));
}

#define LDSM4(r, addr) \
    asm volatile("ldmatrix.sync.aligned.m8n8.x4.shared.b16 {%0,%1,%2,%3}, [%4];" \
        : "=r"((r)[0]), "=r"((r)[1]), "=r"((r)[2]), "=r"((r)[3]) : "r"(addr))
#define LDSM2(r, addr) \
    asm volatile("ldmatrix.sync.aligned.m8n8.x2.shared.b16 {%0,%1}, [%2];" \
        : "=r"((r)[0]), "=r"((r)[1]) : "r"(addr))
#define MMA16816(c, a, b0, b1) \
    asm volatile("mma.sync.aligned.m16n8k16.row.col.f32.f16.f16.f32 " \
        "{%0,%1,%2,%3}, {%4,%5,%6,%7}, {%8,%9}, {%0,%1,%2,%3};" \
        : "+f"((c)[0]), "+f"((c)[1]), "+f"((c)[2]), "+f"((c)[3]) \
        : "r"((a)[0]), "r"((a)[1]), "r"((a)[2]), "r"((a)[3]), "r"(b0), "r"(b1))
#define MMA16808(c, a, b0) \
    asm volatile("mma.sync.aligned.m16n8k8.row.col.f32.f16.f16.f32 " \
        "{%0,%1,%2,%3}, {%4,%5}, {%6}, {%0,%1,%2,%3};" \
        : "+f"((c)[0]), "+f"((c)[1]), "+f"((c)[2]), "+f"((c)[3]) \
        : "r"((a)[0]), "r"((a)[1]), "r"(b0))

__global__ __launch_bounds__(512, 1)
void nlm_hmma_kernel(const float* __restrict__ img, float* __restrict__ out)
{
    extern __shared__ char sm[];
    float*    timg  = (float*)(sm + SM_TIMG);
    float4*   red   = (float4*)(sm + SM_TIMG);     // overlays timg after build
    uint32_t* aux2u = (uint32_t*)(sm + SM_AUX2);
    char*     Yb    = sm + SM_Y;

    const int bid  = blockIdx.x;
    const int tile = bid >> 2, nb = bid & 3;       // 256 rows per CTA
    const int ti = tile / 10, tj = tile % 10;
    const int tid = threadIdx.x;
    const int gb = ti * 32 * IMG + tj * 32;

    // ---- tile image -> smem ----
    for (int i = tid; i < 3 * NPIX; i += 512) {
        int ch = i >> 10, pix = i & 1023;
        timg[i] = img[ch * (IMG * IMG) + gb + (pix >> 5) * IMG + (pix & 31)];
    }
    __syncthreads();

    // ---- build fp16 features Y[1024][72] + pair-interleaved aux ----
    for (int p = tid; p < NPIX; p += 512) {
        int r = p >> 5, c = p & 31;
        __half hl[72];
        float sq = 0.f;
        #pragma unroll
        for (int k = 0; k < 25; k++) {
            if (k == 12) continue;
            int kk = (k < 12) ? k : k - 1;
            int rr = min(max(r + k / 5 - 2, 0), 31);
            int cc = min(max(c + k % 5 - 2, 0), 31);
            int off = rr * 32 + cc;
            #pragma unroll
            for (int ch = 0; ch < 3; ch++) {
                float x = timg[ch * NPIX + off];
                __half h = __float2half_rn(x);
                float xr = __half2float(h);
                sq = fmaf(xr, xr, sq);
                hl[ch * 24 + kk] = h;
            }
        }
        __half2* yrow = (__half2*)(Yb + p * YROWB);
        #pragma unroll
        for (int i = 0; i < 36; i++)
            yrow[i] = __halves2half2(hl[2 * i], hl[2 * i + 1]);
        int ab = (p >> 1) * 8 + (p & 1);
        aux2u[ab + 0] = __float_as_uint(timg[p]);
        aux2u[ab + 2] = __float_as_uint(timg[NPIX + p]);
        aux2u[ab + 4] = __float_as_uint(timg[2 * NPIX + p]);
        aux2u[ab + 6] = __float_as_uint(sq * LOG2E2);       // pre-scaled norm
    }
    __syncthreads();

    // ---- warp geometry: 16 warps = 8 n-subblocks x 2 m-halves ----
    const int wid = tid >> 5, lane = tid & 31;
    const int wn = wid >> 1;
    const int wm2 = wid & 1;
    const int grb = nb * 256 + wn * 32;
    const uint32_t ybase = smem_u32(Yb);

    // ---- A fragments hoisted ----
    uint32_t a[2][4][4], a8[2][2];
    {
        int row = lane & 15;
        int cb  = (lane >> 4) << 4;
        #pragma unroll
        for (int nt = 0; nt < 2; nt++) {
            #pragma unroll
            for (int ks = 0; ks < 4; ks++)
                LDSM4(a[nt][ks], ybase + (uint32_t)(grb + nt * 16 + row) * YROWB + ks * 32 + cb);
            LDSM2(a8[nt], ybase + (uint32_t)(grb + nt * 16 + row) * YROWB + 128);
        }
    }

    // packed scaled row norms + diag row ids, hoisted
    ull  s2[2][2];
    int  gR[2][2];
    #pragma unroll
    for (int nt = 0; nt < 2; nt++)
        #pragma unroll
        for (int h = 0; h < 2; h++) {
            int gr = grb + nt * 16 + h * 8 + (lane >> 2);
            gR[nt][h] = gr;
            float s = __uint_as_float(aux2u[(gr >> 1) * 8 + 6 + (gr & 1)]);
            s2[nt][h] = pack2(s, s);
        }

    const ull neg2 = pack2(NEG2L2, NEG2L2);
    ull den2[2][2] = {{0ull,0ull},{0ull,0ull}};
    ull rr0[2][2]  = {{0ull,0ull},{0ull,0ull}};
    ull rr1[2][2]  = {{0ull,0ull},{0ull,0ull}};
    ull rr2[2][2]  = {{0ull,0ull},{0ull,0ull}};

    // ---- stream m: 8 blocks of 128; warp's 64-col half in 2 groups of 32 ----
    for (int mb = 0; mb < 8; mb++) {
        #pragma unroll
        for (int g = 0; g < 2; g++) {
            const int mgb = mb * 128 + wm2 * 64 + g * 32;
            float c[2][4][4];
            #pragma unroll
            for (int nt = 0; nt < 2; nt++)
                #pragma unroll
                for (int mt = 0; mt < 4; mt++)
                    c[nt][mt][0] = c[nt][mt][1] = c[nt][mt][2] = c[nt][mt][3] = 0.f;

            #pragma unroll
            for (int ks = 0; ks < 4; ks++) {
                uint32_t b[8];
                #pragma unroll
                for (int bt = 0; bt < 2; bt++) {
                    int row = mgb + bt * 16 + (lane & 7) + ((lane >> 4) << 3);
                    int cb  = ks * 32 + (((lane >> 3) & 1) << 4);
                    LDSM4(&b[bt * 4], ybase + (uint32_t)row * YROWB + cb);
                }
                #pragma unroll
                for (int nt = 0; nt < 2; nt++)
                    #pragma unroll
                    for (int mt = 0; mt < 4; mt++) {
                        int bi = (mt >> 1) * 4 + (mt & 1) * 2;
                        MMA16816(c[nt][mt], a[nt][ks], b[bi], b[bi + 1]);
                    }
            }
            {   // k8 tail (cols 64..71)
                uint32_t b8[4];
                int row = mgb + (lane >> 3) * 8 + (lane & 7);
                LDSM4(b8, ybase + (uint32_t)row * YROWB + 128);
                #pragma unroll
                for (int nt = 0; nt < 2; nt++)
                    #pragma unroll
                    for (int mt = 0; mt < 4; mt++)
                        MMA16808(c[nt][mt], a8[nt], b8[mt]);
            }

            // ---- epilogue: packed dd, f32 sqrt, f16x2 ex2 (1 MUFU per 2 pairs) ----
            const bool dg = (mgb == grb);           // warp-uniform diag block
            #pragma unroll
            for (int mt = 0; mt < 4; mt++) {
                const int c0 = mgb + mt * 8 + ((lane & 3) << 1);
                const ulonglong2* ap = (const ulonglong2*)(aux2u + (c0 >> 1) * 8);
                ulonglong2 v01 = ap[0];             // (I0 pair, I1 pair)
                ulonglong2 v23 = ap[1];             // (I2 pair, sq' pair)
                #pragma unroll
                for (int nt = 0; nt < 2; nt++)
                    #pragma unroll
                    for (int h = 0; h < 2; h++) {
                        ull c2  = pack2(c[nt][mt][h * 2], c[nt][mt][h * 2 + 1]);
                        ull dd2 = fma2(c2, neg2, add2(s2[nt][h], v23.y));
                        float2 dd = unpack2(dd2);
                        float t0 = sqrta(dd.x);
                        float t1 = sqrta(dd.y);
                        uint32_t th2 = cvt_h2(t1, t0) ^ 0x80008000u;  // (-t1,-t0)
                        float2 w = h2f2(ex2h2(th2));                  // (w0, w1)
                        if (dg) {                   // kills diag (incl. NaN from d<0)
                            if (gR[nt][h] == c0)     w.x = 0.f;
                            if (gR[nt][h] == c0 + 1) w.y = 0.f;
                        }
                        ull w2 = pack2(w.x, w.y);
                        den2[nt][h] = add2(den2[nt][h], w2);
                        rr0[nt][h] = fma2(w2, v01.x, rr0[nt][h]);
                        rr1[nt][h] = fma2(w2, v01.y, rr1[nt][h]);
                        rr2[nt][h] = fma2(w2, v23.x, rr2[nt][h]);
                    }
            }
        }
    }

    __syncthreads();   // timg dead before red overlay

    // ---- horizontal combine + quad reduce + cross-half via smem ----
    #pragma unroll
    for (int nt = 0; nt < 2; nt++)
        #pragma unroll
        for (int h = 0; h < 2; h++) {
            float2 fd = unpack2(den2[nt][h]);
            float2 f0 = unpack2(rr0[nt][h]);
            float2 f1 = unpack2(rr1[nt][h]);
            float2 f2 = unpack2(rr2[nt][h]);
            float d = fd.x + fd.y, x = f0.x + f0.y, y = f1.x + f1.y, z = f2.x + f2.y;
            #pragma unroll
            for (int off = 1; off <= 2; off <<= 1) {
                d += __shfl_xor_sync(0xFFFFFFFFu, d, off);
                x += __shfl_xor_sync(0xFFFFFFFFu, x, off);
                y += __shfl_xor_sync(0xFFFFFFFFu, y, off);
                z += __shfl_xor_sync(0xFFFFFFFFu, z, off);
            }
            if ((lane & 3) == 0) {
                int rl = wn * 32 + nt * 16 + h * 8 + (lane >> 2);
                red[wm2 * 256 + rl] = make_float4(x, y, z, d);
            }
        }
    __syncthreads();

    if (tid < 256) {
        float4 p0 = red[tid], p1 = red[256 + tid];
        float inv = 1.f / (p0.w + p1.w);
        int n = nb * 256 + tid;
        int gp = gb + (n >> 5) * IMG + (n & 31);
        out[gp]                 = (p0.x + p1.x) * inv;
        out[IMG * IMG + gp]     = (p0.y + p1.y) * inv;
        out[2 * IMG * IMG + gp] = (p0.z + p1.z) * inv;
    }
}

extern "C" void kernel_launch(void* const* d_in, const int* in_sizes, int n_in,
                              void* d_out, int out_size)
{
    (void)in_sizes; (void)n_in; (void)out_size;
    const float* img = (const float*)d_in[0];
    float* out = (float*)d_out;
    cudaFuncSetAttribute(nlm_hmma_kernel, cudaFuncAttributeMaxDynamicSharedMemorySize, SMEM_TOTAL);
    nlm_hmma_kernel<<<400, 512, SMEM_TOTAL>>>(img, out);
}

// round 11
// speedup vs baseline: 1.6596x; 1.2674x over previous
#include <cuda_runtime.h>
#include <cuda_fp16.h>
#include <stdint.h>
#include <math.h>

#define IMG   320
#define NPIX  1024
#define YROWB 144           // 72 halfs; stride%128=16 -> conflict-free ldmatrix

// shared layout (bytes): red overlays timg (timg dead after build)
#define SM_TIMG 0           // 12288 B (red: float4[512]=8KB after main loop)
#define SM_SQS  12288       // float[1024]: sq * log2e^2
#define SM_AUXT 16384       // half[4][1032]: V^T rows {I0, I1, I2, 1}
#define AUXT_STRIDE 1032
#define SM_Y    24704       // half[1024][72] (base%128==0 keeps bank layout)
#define SMEM_TOTAL (SM_Y + NPIX * YROWB)   // 172160

#define LOG2E2  2.0813689810056077f     // (log2 e)^2
#define NEG2L2 (-4.1627379620112153f)   // -2*(log2 e)^2

typedef unsigned long long ull;

__device__ __forceinline__ uint32_t smem_u32(const void* p) {
    uint32_t a;
    asm("{ .reg .u64 t; cvta.to.shared.u64 t, %1; cvt.u32.u64 %0, t; }" : "=r"(a) : "l"(p));
    return a;
}
__device__ __forceinline__ ull fma2(ull a, ull b, ull c) {
    ull d; asm("fma.rn.f32x2 %0, %1, %2, %3;" : "=l"(d) : "l"(a), "l"(b), "l"(c));
    return d;
}
__device__ __forceinline__ ull add2(ull a, ull b) {
    ull d; asm("add.rn.f32x2 %0, %1, %2;" : "=l"(d) : "l"(a), "l"(b));
    return d;
}
__device__ __forceinline__ ull pack2(float lo, float hi) {
    ull d; asm("mov.b64 %0, {%1, %2};" : "=l"(d) : "f"(lo), "f"(hi));
    return d;
}
__device__ __forceinline__ float2 unpack2(ull v) {
    float lo, hi; asm("mov.b64 {%0, %1}, %2;" : "=f"(lo), "=f"(hi) : "l"(v));
    return make_float2(lo, hi);
}
__device__ __forceinline__ float sqrta(float x) {
    float y; asm("sqrt.approx.f32 %0, %1;" : "=f"(y) : "f"(x)); return y;
}
__device__ __forceinline__ uint32_t cvt_h2(float hi, float lo) {   // h1=hi, h0=lo
    uint32_t r; asm("cvt.rn.f16x2.f32 %0, %1, %2;" : "=r"(r) : "f"(hi), "f"(lo));
    return r;
}
__device__ __forceinline__ uint32_t ex2h2(uint32_t a) {            // MUFU, 2 results
    uint32_t r; asm("ex2.approx.f16x2 %0, %1;" : "=r"(r) : "r"(a));
    return r;
}

#define LDSM4(r, addr) \
    asm volatile("ldmatrix.sync.aligned.m8n8.x4.shared.b16 {%0,%1,%2,%3}, [%4];" \
        : "=r"((r)[0]), "=r"((r)[1]), "=r"((r)[2]), "=r"((r)[3]) : "r"(addr))
#define LDSM2(r, addr) \
    asm volatile("ldmatrix.sync.aligned.m8n8.x2.shared.b16 {%0,%1}, [%2];" \
        : "=r"((r)[0]), "=r"((r)[1]) : "r"(addr))
#define MMA16816(c, a, b0, b1) \
    asm volatile("mma.sync.aligned.m16n8k16.row.col.f32.f16.f16.f32 " \
        "{%0,%1,%2,%3}, {%4,%5,%6,%7}, {%8,%9}, {%0,%1,%2,%3};" \
        : "+f"((c)[0]), "+f"((c)[1]), "+f"((c)[2]), "+f"((c)[3]) \
        : "r"((a)[0]), "r"((a)[1]), "r"((a)[2]), "r"((a)[3]), "r"(b0), "r"(b1))
#define MMA16808(c, a, b0) \
    asm volatile("mma.sync.aligned.m16n8k8.row.col.f32.f16.f16.f32 " \
        "{%0,%1,%2,%3}, {%4,%5}, {%6}, {%0,%1,%2,%3};" \
        : "+f"((c)[0]), "+f"((c)[1]), "+f"((c)[2]), "+f"((c)[3]) \
        : "r"((a)[0]), "r"((a)[1]), "r"(b0))

__global__ __launch_bounds__(512, 1)
void nlm_hmma_kernel(const float* __restrict__ img, float* __restrict__ out)
{
    extern __shared__ char sm[];
    float*   timg = (float*)(sm + SM_TIMG);
    float4*  red  = (float4*)(sm + SM_TIMG);      // overlays timg after main loop
    float*   sqs  = (float*)(sm + SM_SQS);
    __half*  auxT = (__half*)(sm + SM_AUXT);
    char*    Yb   = sm + SM_Y;

    const int bid  = blockIdx.x;
    const int tile = bid >> 2, nb = bid & 3;      // 256 rows per CTA
    const int ti = tile / 10, tj = tile % 10;
    const int tid = threadIdx.x;
    const int gb = ti * 32 * IMG + tj * 32;

    // ---- tile image -> smem ----
    for (int i = tid; i < 3 * NPIX; i += 512) {
        int ch = i >> 10, pix = i & 1023;
        timg[i] = img[ch * (IMG * IMG) + gb + (pix >> 5) * IMG + (pix & 31)];
    }
    __syncthreads();

    // ---- build fp16 features Y[1024][72] + V^T (fp16) + scaled norms ----
    for (int p = tid; p < NPIX; p += 512) {
        int r = p >> 5, c = p & 31;
        __half hl[72];
        float sq = 0.f;
        #pragma unroll
        for (int k = 0; k < 25; k++) {
            if (k == 12) continue;
            int kk = (k < 12) ? k : k - 1;
            int rr = min(max(r + k / 5 - 2, 0), 31);
            int cc = min(max(c + k % 5 - 2, 0), 31);
            int off = rr * 32 + cc;
            #pragma unroll
            for (int ch = 0; ch < 3; ch++) {
                float x = timg[ch * NPIX + off];
                __half h = __float2half_rn(x);
                float xr = __half2float(h);
                sq = fmaf(xr, xr, sq);
                hl[ch * 24 + kk] = h;
            }
        }
        __half2* yrow = (__half2*)(Yb + p * YROWB);
        #pragma unroll
        for (int i = 0; i < 36; i++)
            yrow[i] = __halves2half2(hl[2 * i], hl[2 * i + 1]);
        sqs[p] = sq * LOG2E2;
        auxT[0 * AUXT_STRIDE + p] = __float2half_rn(timg[p]);
        auxT[1 * AUXT_STRIDE + p] = __float2half_rn(timg[NPIX + p]);
        auxT[2 * AUXT_STRIDE + p] = __float2half_rn(timg[2 * NPIX + p]);
        auxT[3 * AUXT_STRIDE + p] = __float2half_rn(1.f);
    }
    __syncthreads();

    // ---- warp geometry: 16 warps = 8 n-subblocks x 2 m-halves ----
    const int wid = tid >> 5, lane = tid & 31;
    const int wn = wid >> 1;
    const int wm2 = wid & 1;
    const int grb = nb * 256 + wn * 32;
    const uint32_t ybase = smem_u32(Yb);
    const int n4 = (lane >> 2) & 3;               // V col (0..3), lanes 4-7 duplicate
    const __half* vtrow = auxT + n4 * AUXT_STRIDE;

    // ---- A fragments hoisted ----
    uint32_t a[2][4][4], a8[2][2];
    {
        int row = lane & 15;
        int cb  = (lane >> 4) << 4;
        #pragma unroll
        for (int nt = 0; nt < 2; nt++) {
            #pragma unroll
            for (int ks = 0; ks < 4; ks++)
                LDSM4(a[nt][ks], ybase + (uint32_t)(grb + nt * 16 + row) * YROWB + ks * 32 + cb);
            LDSM2(a8[nt], ybase + (uint32_t)(grb + nt * 16 + row) * YROWB + 128);
        }
    }

    // packed scaled row norms + diag row ids, hoisted
    ull  s2[2][2];
    int  gR[2][2];
    #pragma unroll
    for (int nt = 0; nt < 2; nt++)
        #pragma unroll
        for (int h = 0; h < 2; h++) {
            int gr = grb + nt * 16 + h * 8 + (lane >> 2);
            gR[nt][h] = gr;
            float s = sqs[gr];
            s2[nt][h] = pack2(s, s);
        }

    const ull neg2 = pack2(NEG2L2, NEG2L2);
    float O[2][4] = {{0.f,0.f,0.f,0.f},{0.f,0.f,0.f,0.f}};  // cols: S0,S1,S2,den(,dup)

    // ---- stream m: 8 blocks of 128; warp's 64-col half in 2 groups of 32 ----
    for (int mb = 0; mb < 8; mb++) {
        #pragma unroll
        for (int g = 0; g < 2; g++) {
            const int mgb = mb * 128 + wm2 * 64 + g * 32;
            float c[2][4][4];
            #pragma unroll
            for (int nt = 0; nt < 2; nt++)
                #pragma unroll
                for (int mt = 0; mt < 4; mt++)
                    c[nt][mt][0] = c[nt][mt][1] = c[nt][mt][2] = c[nt][mt][3] = 0.f;

            #pragma unroll
            for (int ks = 0; ks < 4; ks++) {
                uint32_t b[8];
                #pragma unroll
                for (int bt = 0; bt < 2; bt++) {
                    int row = mgb + bt * 16 + (lane & 7) + ((lane >> 4) << 3);
                    int cb  = ks * 32 + (((lane >> 3) & 1) << 4);
                    LDSM4(&b[bt * 4], ybase + (uint32_t)row * YROWB + cb);
                }
                #pragma unroll
                for (int nt = 0; nt < 2; nt++)
                    #pragma unroll
                    for (int mt = 0; mt < 4; mt++) {
                        int bi = (mt >> 1) * 4 + (mt & 1) * 2;
                        MMA16816(c[nt][mt], a[nt][ks], b[bi], b[bi + 1]);
                    }
            }
            {   // k8 tail (cols 64..71)
                uint32_t b8[4];
                int row = mgb + (lane >> 3) * 8 + (lane & 7);
                LDSM4(b8, ybase + (uint32_t)row * YROWB + 128);
                #pragma unroll
                for (int nt = 0; nt < 2; nt++)
                    #pragma unroll
                    for (int mt = 0; mt < 4; mt++)
                        MMA16808(c[nt][mt], a8[nt], b8[mt]);
            }

            // ---- weights into fp16 P fragments (no unpack, no scalar accum) ----
            const bool dg = (mgb == grb);           // warp-uniform diag block
            uint32_t wreg[4][2][2];
            #pragma unroll
            for (int mt = 0; mt < 4; mt++) {
                const int c0 = mgb + mt * 8 + ((lane & 3) << 1);
                const ull qm2 = *(const ull*)(sqs + c0);   // LDS.64 (pair of norms)
                #pragma unroll
                for (int nt = 0; nt < 2; nt++)
                    #pragma unroll
                    for (int h = 0; h < 2; h++) {
                        ull c2  = pack2(c[nt][mt][h * 2], c[nt][mt][h * 2 + 1]);
                        ull dd2 = fma2(c2, neg2, add2(s2[nt][h], qm2));
                        float2 dd = unpack2(dd2);
                        float t0 = sqrta(dd.x);
                        float t1 = sqrta(dd.y);
                        uint32_t w = ex2h2(cvt_h2(t1, t0) ^ 0x80008000u);
                        if (dg) {                   // kill diag (incl. NaN halves)
                            if (gR[nt][h] == c0)     w &= 0xFFFF0000u;
                            if (gR[nt][h] == c0 + 1) w &= 0x0000FFFFu;
                        }
                        wreg[mt][nt][h] = w;
                    }
            }

            // ---- P @ V : 2 k16 steps x 2 nt, V = [I0,I1,I2,1] fp16 ----
            #pragma unroll
            for (int ks2 = 0; ks2 < 2; ks2++) {
                const int mk0 = mgb + ks2 * 16 + ((lane & 3) << 1);
                uint32_t b0 = *(const uint32_t*)(vtrow + mk0);
                uint32_t b1 = *(const uint32_t*)(vtrow + mk0 + 8);
                #pragma unroll
                for (int nt = 0; nt < 2; nt++) {
                    uint32_t pa[4] = { wreg[ks2 * 2][nt][0],     wreg[ks2 * 2][nt][1],
                                       wreg[ks2 * 2 + 1][nt][0], wreg[ks2 * 2 + 1][nt][1] };
                    MMA16816(O[nt], pa, b0, b1);
                }
            }
        }
    }

    // ---- write per-half partials (timg dead; red overlay) ----
    const int j = lane & 3;
    #pragma unroll
    for (int nt = 0; nt < 2; nt++) {
        if (j < 2) {
            int rl = wn * 32 + nt * 16 + (lane >> 2);
            ((float2*)&red[wm2 * 256 + rl])[j]     = make_float2(O[nt][0], O[nt][1]);
            ((float2*)&red[wm2 * 256 + rl + 8])[j] = make_float2(O[nt][2], O[nt][3]);
        }
    }
    __syncthreads();

    if (tid < 256) {
        float4 p0 = red[tid], p1 = red[256 + tid];
        float inv = 1.f / (p0.w + p1.w);
        int n = nb * 256 + tid;
        int gp = gb + (n >> 5) * IMG + (n & 31);
        out[gp]                 = (p0.x + p1.x) * inv;
        out[IMG * IMG + gp]     = (p0.y + p1.y) * inv;
        out[2 * IMG * IMG + gp] = (p0.z + p1.z) * inv;
    }
}

extern "C" void kernel_launch(void* const* d_in, const int* in_sizes, int n_in,
                              void* d_out, int out_size)
{
    (void)in_sizes; (void)n_in; (void)out_size;
    const float* img = (const float*)d_in[0];
    float* out = (float*)d_out;
    cudaFuncSetAttribute(nlm_hmma_kernel, cudaFuncAttributeMaxDynamicSharedMemorySize, SMEM_TOTAL);
    nlm_hmma_kernel<<<400, 512, SMEM_TOTAL>>>(img, out);
}